// round 1
// baseline (speedup 1.0000x reference)
#include <cuda_runtime.h>

#define BB 512   // batch
#define TT 256   // seq len
#define HH 64    // hidden
#define GG 256   // 4*H gates
#define DD 64    // input/output dim

// Scratch (static __device__ arrays — allocation-free per harness rules)
__device__ float g_xg[(size_t)TT * BB * GG];   // 134 MB gate pre-activations [T][B][G]
__device__ float g_hseq[(size_t)TT * BB * HH]; // 33.5 MB hidden sequence [T][B][H]
__device__ float g_lat[BB * HH];               // encoder latent [B][H]
__device__ float g_xgc[BB * GG];               // dec0 constant xg [B][G]

__device__ __forceinline__ float fsigm(float x) {
    return __fdividef(1.0f, 1.0f + __expf(-x));
}
__device__ __forceinline__ float ftanh(float x) {
    // 1 - 2/(e^{2x}+1); correct saturation at +/-inf, ~1e-7 abs error
    return 1.0f - __fdividef(2.0f, __expf(2.0f * x) + 1.0f);
}

// ---------------------------------------------------------------------------
// xg GEMM: out[n][g] = sum_k X[b(n),t(n)][k] * W[g][k] + bih[g] + bhh[g]
// n = t*BB + b. X element offset = b*st_b + t*st_t + k. K = 64 fixed.
// Tile: 128 rows x 64 gates per block, 256 threads, 8x4 micro-tile.
// ---------------------------------------------------------------------------
__global__ __launch_bounds__(256) void xg_gemm(
    const float* __restrict__ X, int st_b, int st_t,
    const float* __restrict__ W,
    const float* __restrict__ bih, const float* __restrict__ bhh,
    float* __restrict__ out)
{
    __shared__ float Xs[64][128];  // [k][m]
    __shared__ float Ws[64][64];   // [k][g]
    const int tid  = threadIdx.x;
    const int row0 = blockIdx.x * 128;
    const int col0 = blockIdx.y * 64;

    // Load X tile, transposed into [k][m]
    #pragma unroll
    for (int i = 0; i < 8; i++) {
        int idx = tid + i * 256;       // 0..2047
        int m   = idx & 127;
        int k4  = idx >> 7;            // 0..15
        int n   = row0 + m;
        int b   = n & (BB - 1);
        int t   = n >> 9;              // n / 512
        float4 v = *(const float4*)(X + (size_t)b * st_b + (size_t)t * st_t + k4 * 4);
        Xs[k4*4+0][m] = v.x; Xs[k4*4+1][m] = v.y;
        Xs[k4*4+2][m] = v.z; Xs[k4*4+3][m] = v.w;
    }
    // Load W tile (64 gate rows), transposed into [k][g]
    #pragma unroll
    for (int i = 0; i < 4; i++) {
        int idx = tid + i * 256;       // 0..1023
        int m   = idx & 63;
        int k4  = idx >> 6;            // 0..15
        float4 v = *(const float4*)(W + (size_t)(col0 + m) * 64 + k4 * 4);
        Ws[k4*4+0][m] = v.x; Ws[k4*4+1][m] = v.y;
        Ws[k4*4+2][m] = v.z; Ws[k4*4+3][m] = v.w;
    }
    __syncthreads();

    const int tx = tid & 15;   // gate group (4 gates)
    const int ty = tid >> 4;   // row group (8 rows)

    float4 bi = *(const float4*)(bih + col0 + tx * 4);
    float4 bh = *(const float4*)(bhh + col0 + tx * 4);
    const float bs0 = bi.x + bh.x, bs1 = bi.y + bh.y;
    const float bs2 = bi.z + bh.z, bs3 = bi.w + bh.w;

    float acc[8][4];
    #pragma unroll
    for (int r = 0; r < 8; r++) {
        acc[r][0] = bs0; acc[r][1] = bs1; acc[r][2] = bs2; acc[r][3] = bs3;
    }

    #pragma unroll 16
    for (int k = 0; k < 64; k++) {
        float4 a0 = *(const float4*)&Xs[k][ty * 8];
        float4 a1 = *(const float4*)&Xs[k][ty * 8 + 4];
        float4 wv = *(const float4*)&Ws[k][tx * 4];
        float a[8] = {a0.x, a0.y, a0.z, a0.w, a1.x, a1.y, a1.z, a1.w};
        #pragma unroll
        for (int r = 0; r < 8; r++) {
            acc[r][0] = fmaf(a[r], wv.x, acc[r][0]);
            acc[r][1] = fmaf(a[r], wv.y, acc[r][1]);
            acc[r][2] = fmaf(a[r], wv.z, acc[r][2]);
            acc[r][3] = fmaf(a[r], wv.w, acc[r][3]);
        }
    }
    #pragma unroll
    for (int r = 0; r < 8; r++) {
        float4 o = make_float4(acc[r][0], acc[r][1], acc[r][2], acc[r][3]);
        *(float4*)(out + (size_t)(row0 + ty * 8 + r) * GG + col0 + tx * 4) = o;
    }
}

// ---------------------------------------------------------------------------
// LSTM recurrence scan. One block = 4 batch elements, 256 threads.
// Thread tid owns gate row Whh[tid][:] in registers; computes that gate for
// all 4 batch elems each step. Cell update: thread (bl=tid>>6, j=tid&63).
// XGC: xg constant over time (dec0). SMODE: 0 = store full hseq,
// 1 = store last h only (enc1 -> latent), 2 = fused FC output (dec1).
// ---------------------------------------------------------------------------
template<int XGC, int SMODE>
__global__ __launch_bounds__(256) void lstm_scan(
    const float* __restrict__ xg,
    const float* __restrict__ Whh,
    float* __restrict__ hout,
    const float* __restrict__ fcW,
    const float* __restrict__ fcb)
{
    __shared__ float h_sh[4][HH];
    __shared__ float gates_sh[4][GG];
    __shared__ float fcb_sh[DD];

    const int tid = threadIdx.x;
    const int b0  = blockIdx.x * 4;
    const int bl  = tid >> 6;
    const int j   = tid & 63;

    // Recurrent weight row in registers
    float w[64];
    #pragma unroll
    for (int k = 0; k < 64; k += 4) {
        float4 v = *(const float4*)(Whh + (size_t)tid * 64 + k);
        w[k] = v.x; w[k+1] = v.y; w[k+2] = v.z; w[k+3] = v.w;
    }
    float fw[64];
    if (SMODE == 2) {
        #pragma unroll
        for (int k = 0; k < 64; k += 4) {
            float4 v = *(const float4*)(fcW + (size_t)j * 64 + k);
            fw[k] = v.x; fw[k+1] = v.y; fw[k+2] = v.z; fw[k+3] = v.w;
        }
        if (tid < DD) fcb_sh[tid] = fcb[tid];
    }

    if (tid < HH) {
        h_sh[0][tid] = 0.f; h_sh[1][tid] = 0.f;
        h_sh[2][tid] = 0.f; h_sh[3][tid] = 0.f;
    }
    float c = 0.f;

    // xg for t=0 (or the constant xg)
    float xn0, xn1, xn2, xn3;
    {
        const float* p = xg + (size_t)b0 * GG + tid;
        xn0 = p[0]; xn1 = p[GG]; xn2 = p[2 * GG]; xn3 = p[3 * GG];
    }
    __syncthreads();

    const int gt = tid >> 6;  // 0:i 1:f 2:g 3:o — warp-uniform

    for (int t = 0; t < TT; t++) {
        float a0 = xn0, a1 = xn1, a2 = xn2, a3 = xn3;
        if (!XGC && t + 1 < TT) {  // prefetch next step's xg
            const float* p = xg + ((size_t)(t + 1) * BB + b0) * GG + tid;
            xn0 = p[0]; xn1 = p[GG]; xn2 = p[2 * GG]; xn3 = p[3 * GG];
        }
        const float4* h40 = (const float4*)h_sh[0];
        const float4* h41 = (const float4*)h_sh[1];
        const float4* h42 = (const float4*)h_sh[2];
        const float4* h43 = (const float4*)h_sh[3];
        #pragma unroll
        for (int k4 = 0; k4 < 16; k4++) {
            float4 h0 = h40[k4], h1 = h41[k4], h2 = h42[k4], h3 = h43[k4];
            float w0 = w[4*k4], w1 = w[4*k4+1], w2 = w[4*k4+2], w3 = w[4*k4+3];
            a0 = fmaf(h0.x, w0, a0); a0 = fmaf(h0.y, w1, a0);
            a0 = fmaf(h0.z, w2, a0); a0 = fmaf(h0.w, w3, a0);
            a1 = fmaf(h1.x, w0, a1); a1 = fmaf(h1.y, w1, a1);
            a1 = fmaf(h1.z, w2, a1); a1 = fmaf(h1.w, w3, a1);
            a2 = fmaf(h2.x, w0, a2); a2 = fmaf(h2.y, w1, a2);
            a2 = fmaf(h2.z, w2, a2); a2 = fmaf(h2.w, w3, a2);
            a3 = fmaf(h3.x, w0, a3); a3 = fmaf(h3.y, w1, a3);
            a3 = fmaf(h3.z, w2, a3); a3 = fmaf(h3.w, w3, a3);
        }
        float v0, v1, v2, v3;
        if (gt == 2) { v0 = ftanh(a0); v1 = ftanh(a1); v2 = ftanh(a2); v3 = ftanh(a3); }
        else         { v0 = fsigm(a0); v1 = fsigm(a1); v2 = fsigm(a2); v3 = fsigm(a3); }
        gates_sh[0][tid] = v0; gates_sh[1][tid] = v1;
        gates_sh[2][tid] = v2; gates_sh[3][tid] = v3;
        __syncthreads();

        // Cell update: thread (bl, j)
        {
            float gi = gates_sh[bl][j];
            float gf = gates_sh[bl][HH + j];
            float gc = gates_sh[bl][2 * HH + j];
            float go = gates_sh[bl][3 * HH + j];
            c = fmaf(gf, c, gi * gc);
            float h = go * ftanh(c);
            h_sh[bl][j] = h;
            if (SMODE == 0)
                hout[((size_t)t * BB + b0 + bl) * HH + j] = h;
            if (SMODE == 1 && t == TT - 1)
                hout[(size_t)(b0 + bl) * HH + j] = h;
        }
        __syncthreads();

        if (SMODE == 2) {  // fused FC: out[b][t][d] = h . fcW[d] + fcb[d]
            float s = fcb_sh[j];
            const float4* hb = (const float4*)h_sh[bl];
            #pragma unroll
            for (int k4 = 0; k4 < 16; k4++) {
                float4 hv = hb[k4];
                s = fmaf(hv.x, fw[4*k4],   s);
                s = fmaf(hv.y, fw[4*k4+1], s);
                s = fmaf(hv.z, fw[4*k4+2], s);
                s = fmaf(hv.w, fw[4*k4+3], s);
            }
            hout[((size_t)(b0 + bl) * TT + t) * DD + j] = s;
        }
    }
}

// ---------------------------------------------------------------------------
extern "C" void kernel_launch(void* const* d_in, const int* in_sizes, int n_in,
                              void* d_out, int out_size)
{
    (void)in_sizes; (void)n_in; (void)out_size;
    const float* x     = (const float*)d_in[0];
    const float* eWih0 = (const float*)d_in[1];
    const float* eWhh0 = (const float*)d_in[2];
    const float* ebih0 = (const float*)d_in[3];
    const float* ebhh0 = (const float*)d_in[4];
    const float* eWih1 = (const float*)d_in[5];
    const float* eWhh1 = (const float*)d_in[6];
    const float* ebih1 = (const float*)d_in[7];
    const float* ebhh1 = (const float*)d_in[8];
    const float* dWih0 = (const float*)d_in[9];
    const float* dWhh0 = (const float*)d_in[10];
    const float* dbih0 = (const float*)d_in[11];
    const float* dbhh0 = (const float*)d_in[12];
    const float* dWih1 = (const float*)d_in[13];
    const float* dWhh1 = (const float*)d_in[14];
    const float* dbih1 = (const float*)d_in[15];
    const float* dbhh1 = (const float*)d_in[16];
    const float* fcW   = (const float*)d_in[17];
    const float* fcb   = (const float*)d_in[18];
    float* out = (float*)d_out;

    float *xgp, *hseqp, *latp, *xgcp;
    cudaGetSymbolAddress((void**)&xgp,   g_xg);
    cudaGetSymbolAddress((void**)&hseqp, g_hseq);
    cudaGetSymbolAddress((void**)&latp,  g_lat);
    cudaGetSymbolAddress((void**)&xgcp,  g_xgc);

    dim3 gbig(TT * BB / 128, GG / 64);  // (1024, 4)
    dim3 gsm(BB / 128, GG / 64);        // (4, 4)
    dim3 gscan(BB / 4);                 // 128 blocks

    // Encoder layer 0: xg from x [B][T][64], then scan -> hseq
    xg_gemm<<<gbig, 256>>>(x, TT * 64, 64, eWih0, ebih0, ebhh0, xgp);
    lstm_scan<0, 0><<<gscan, 256>>>(xgp, eWhh0, hseqp, nullptr, nullptr);

    // Encoder layer 1: xg from hseq [T][B][64], scan -> latent (last h only)
    xg_gemm<<<gbig, 256>>>(hseqp, 64, BB * 64, eWih1, ebih1, ebhh1, xgp);
    lstm_scan<0, 1><<<gscan, 256>>>(xgp, eWhh1, latp, nullptr, nullptr);

    // Decoder layer 0: input is constant latent -> single [B][G] xg
    xg_gemm<<<gsm, 256>>>(latp, 64, 0, dWih0, dbih0, dbhh0, xgcp);
    lstm_scan<1, 0><<<gscan, 256>>>(xgcp, dWhh0, hseqp, nullptr, nullptr);

    // Decoder layer 1: xg from hseq, scan with fused FC -> d_out [B][T][64]
    xg_gemm<<<gbig, 256>>>(hseqp, 64, BB * 64, dWih1, dbih1, dbhh1, xgp);
    lstm_scan<0, 2><<<gscan, 256>>>(xgp, dWhh1, out, fcW, fcb);
}

// round 2
// speedup vs baseline: 1.2695x; 1.2695x over previous
#include <cuda_runtime.h>

#define BB 512   // batch
#define TT 256   // seq len
#define HH 64    // hidden
#define GG 256   // 4*H gates
#define DD 64    // input/output dim

// Scratch (static __device__ arrays — allocation-free per harness rules)
__device__ float g_xg[(size_t)TT * BB * GG];   // gate pre-activations [T][B][G]
__device__ float g_hseq[(size_t)TT * BB * HH]; // hidden sequence [T][B][H]
__device__ float g_lat[BB * HH];               // encoder latent [B][H]
__device__ float g_xgc[BB * GG];               // dec0 constant xg [B][G]

typedef unsigned long long u64;

__device__ __forceinline__ u64 ffma2(u64 a, u64 b, u64 c) {
    u64 d;
    asm("fma.rn.f32x2 %0, %1, %2, %3;" : "=l"(d) : "l"(a), "l"(b), "l"(c));
    return d;
}
__device__ __forceinline__ u64 pk2(float lo, float hi) {
    u64 v;
    asm("mov.b64 %0, {%1, %2};" : "=l"(v) : "f"(lo), "f"(hi));
    return v;
}
__device__ __forceinline__ float2 up2(u64 v) {
    float lo, hi;
    asm("mov.b64 {%0, %1}, %2;" : "=f"(lo), "=f"(hi) : "l"(v));
    return make_float2(lo, hi);
}

__device__ __forceinline__ float fsigm(float x) {
    return __fdividef(1.0f, 1.0f + __expf(-x));
}
__device__ __forceinline__ float ftanh(float x) {
    return 1.0f - __fdividef(2.0f, __expf(2.0f * x) + 1.0f);
}

// ---------------------------------------------------------------------------
// xg GEMM: out[n][g] = sum_k X[b(n),t(n)][k] * W[g][k] + bih[g] + bhh[g]
// n = t*BB + b. X element offset = b*st_b + t*st_t + k. K = 64 fixed.
// ---------------------------------------------------------------------------
__global__ __launch_bounds__(256) void xg_gemm(
    const float* __restrict__ X, int st_b, int st_t,
    const float* __restrict__ W,
    const float* __restrict__ bih, const float* __restrict__ bhh,
    float* __restrict__ out)
{
    __shared__ float Xs[64][128];  // [k][m]
    __shared__ float Ws[64][64];   // [k][g]
    const int tid  = threadIdx.x;
    const int row0 = blockIdx.x * 128;
    const int col0 = blockIdx.y * 64;

    #pragma unroll
    for (int i = 0; i < 8; i++) {
        int idx = tid + i * 256;
        int m   = idx & 127;
        int k4  = idx >> 7;
        int n   = row0 + m;
        int b   = n & (BB - 1);
        int t   = n >> 9;
        float4 v = *(const float4*)(X + (size_t)b * st_b + (size_t)t * st_t + k4 * 4);
        Xs[k4*4+0][m] = v.x; Xs[k4*4+1][m] = v.y;
        Xs[k4*4+2][m] = v.z; Xs[k4*4+3][m] = v.w;
    }
    #pragma unroll
    for (int i = 0; i < 4; i++) {
        int idx = tid + i * 256;
        int m   = idx & 63;
        int k4  = idx >> 6;
        float4 v = *(const float4*)(W + (size_t)(col0 + m) * 64 + k4 * 4);
        Ws[k4*4+0][m] = v.x; Ws[k4*4+1][m] = v.y;
        Ws[k4*4+2][m] = v.z; Ws[k4*4+3][m] = v.w;
    }
    __syncthreads();

    const int tx = tid & 15;
    const int ty = tid >> 4;

    float4 bi = *(const float4*)(bih + col0 + tx * 4);
    float4 bh = *(const float4*)(bhh + col0 + tx * 4);
    const float bs0 = bi.x + bh.x, bs1 = bi.y + bh.y;
    const float bs2 = bi.z + bh.z, bs3 = bi.w + bh.w;

    float acc[8][4];
    #pragma unroll
    for (int r = 0; r < 8; r++) {
        acc[r][0] = bs0; acc[r][1] = bs1; acc[r][2] = bs2; acc[r][3] = bs3;
    }

    #pragma unroll 16
    for (int k = 0; k < 64; k++) {
        float4 a0 = *(const float4*)&Xs[k][ty * 8];
        float4 a1 = *(const float4*)&Xs[k][ty * 8 + 4];
        float4 wv = *(const float4*)&Ws[k][tx * 4];
        float a[8] = {a0.x, a0.y, a0.z, a0.w, a1.x, a1.y, a1.z, a1.w};
        #pragma unroll
        for (int r = 0; r < 8; r++) {
            acc[r][0] = fmaf(a[r], wv.x, acc[r][0]);
            acc[r][1] = fmaf(a[r], wv.y, acc[r][1]);
            acc[r][2] = fmaf(a[r], wv.z, acc[r][2]);
            acc[r][3] = fmaf(a[r], wv.w, acc[r][3]);
        }
    }
    #pragma unroll
    for (int r = 0; r < 8; r++) {
        float4 o = make_float4(acc[r][0], acc[r][1], acc[r][2], acc[r][3]);
        *(float4*)(out + (size_t)(row0 + ty * 8 + r) * GG + col0 + tx * 4) = o;
    }
}

// ---------------------------------------------------------------------------
// FC GEMM: out[b][t][d] = hseq_row(n=t*BB+b) . fcW[d] + fcb[d]
// X = hseq as [n][64] contiguous. 128 rows x 64 cols per block.
// ---------------------------------------------------------------------------
__global__ __launch_bounds__(256) void fc_gemm(
    const float* __restrict__ X,
    const float* __restrict__ W,
    const float* __restrict__ bias,
    float* __restrict__ out)
{
    __shared__ float Xs[64][128];
    __shared__ float Ws[64][64];
    const int tid  = threadIdx.x;
    const int row0 = blockIdx.x * 128;

    #pragma unroll
    for (int i = 0; i < 8; i++) {
        int idx = tid + i * 256;
        int m   = idx & 127;
        int k4  = idx >> 7;
        float4 v = *(const float4*)(X + (size_t)(row0 + m) * 64 + k4 * 4);
        Xs[k4*4+0][m] = v.x; Xs[k4*4+1][m] = v.y;
        Xs[k4*4+2][m] = v.z; Xs[k4*4+3][m] = v.w;
    }
    #pragma unroll
    for (int i = 0; i < 4; i++) {
        int idx = tid + i * 256;
        int m   = idx & 63;
        int k4  = idx >> 6;
        float4 v = *(const float4*)(W + (size_t)m * 64 + k4 * 4);
        Ws[k4*4+0][m] = v.x; Ws[k4*4+1][m] = v.y;
        Ws[k4*4+2][m] = v.z; Ws[k4*4+3][m] = v.w;
    }
    __syncthreads();

    const int tx = tid & 15;
    const int ty = tid >> 4;

    float4 bv = *(const float4*)(bias + tx * 4);
    float acc[8][4];
    #pragma unroll
    for (int r = 0; r < 8; r++) {
        acc[r][0] = bv.x; acc[r][1] = bv.y; acc[r][2] = bv.z; acc[r][3] = bv.w;
    }

    #pragma unroll 16
    for (int k = 0; k < 64; k++) {
        float4 a0 = *(const float4*)&Xs[k][ty * 8];
        float4 a1 = *(const float4*)&Xs[k][ty * 8 + 4];
        float4 wv = *(const float4*)&Ws[k][tx * 4];
        float a[8] = {a0.x, a0.y, a0.z, a0.w, a1.x, a1.y, a1.z, a1.w};
        #pragma unroll
        for (int r = 0; r < 8; r++) {
            acc[r][0] = fmaf(a[r], wv.x, acc[r][0]);
            acc[r][1] = fmaf(a[r], wv.y, acc[r][1]);
            acc[r][2] = fmaf(a[r], wv.z, acc[r][2]);
            acc[r][3] = fmaf(a[r], wv.w, acc[r][3]);
        }
    }
    #pragma unroll
    for (int r = 0; r < 8; r++) {
        int n = row0 + ty * 8 + r;
        int b = n & (BB - 1);
        int t = n >> 9;
        float4 o = make_float4(acc[r][0], acc[r][1], acc[r][2], acc[r][3]);
        *(float4*)(out + ((size_t)b * TT + t) * DD + tx * 4) = o;
    }
}

// ---------------------------------------------------------------------------
// LSTM recurrence scan. One block = 2 batch elements, 256 threads, occ 2/SM.
// Thread tid owns gate row Whh[tid][:] as 32 packed f32x2 regs; per step does
// 64 FFMA2 (k-pair packed dot) for 2 batches. Cell update: tid<128.
// XGC: xg constant over time (dec0). SMODE: 0 = store full hseq,
// 1 = store last h only (enc1 -> latent).
// ---------------------------------------------------------------------------
template<int XGC, int SMODE>
__global__ __launch_bounds__(256, 2) void lstm_scan(
    const float* __restrict__ xg,
    const float* __restrict__ Whh,
    float* __restrict__ hout)
{
    __shared__ float h_sh[2][HH];
    __shared__ float gates_sh[2][GG];

    const int tid = threadIdx.x;
    const int b0  = blockIdx.x * 2;
    const int bl  = tid >> 6;   // for cell update (tid < 128): 0/1
    const int j   = tid & 63;

    // Recurrent weight row as packed f32x2 pairs over k
    u64 w2[32];
    {
        const ulonglong2* wp = (const ulonglong2*)(Whh + (size_t)tid * 64);
        #pragma unroll
        for (int i = 0; i < 16; i++) {
            ulonglong2 v = wp[i];
            w2[2*i] = v.x; w2[2*i+1] = v.y;
        }
    }

    if (tid < HH) { h_sh[0][tid] = 0.f; h_sh[1][tid] = 0.f; }
    float c = 0.f;

    float xn0, xn1;
    {
        const float* p = xg + (size_t)b0 * GG + tid;
        xn0 = p[0]; xn1 = p[GG];
    }
    __syncthreads();

    const int gt = tid >> 6;  // 0:i 1:f 2:g 3:o — warp-uniform

    for (int t = 0; t < TT; t++) {
        u64 a0a = pk2(xn0, 0.f), a0b = 0ull;
        u64 a1a = pk2(xn1, 0.f), a1b = 0ull;
        if (!XGC && t + 1 < TT) {  // prefetch next step's xg
            const float* p = xg + ((size_t)(t + 1) * BB + b0) * GG + tid;
            xn0 = p[0]; xn1 = p[GG];
        }
        const ulonglong2* h0p = (const ulonglong2*)h_sh[0];
        const ulonglong2* h1p = (const ulonglong2*)h_sh[1];
        #pragma unroll
        for (int k = 0; k < 16; k++) {
            ulonglong2 hq0 = h0p[k];
            ulonglong2 hq1 = h1p[k];
            a0a = ffma2(hq0.x, w2[2*k],     a0a);
            a0b = ffma2(hq0.y, w2[2*k + 1], a0b);
            a1a = ffma2(hq1.x, w2[2*k],     a1a);
            a1b = ffma2(hq1.y, w2[2*k + 1], a1b);
        }
        float2 s0a = up2(a0a), s0b = up2(a0b);
        float2 s1a = up2(a1a), s1b = up2(a1b);
        float A0 = (s0a.x + s0a.y) + (s0b.x + s0b.y);
        float A1 = (s1a.x + s1a.y) + (s1b.x + s1b.y);

        float v0, v1;
        if (gt == 2) { v0 = ftanh(A0); v1 = ftanh(A1); }
        else         { v0 = fsigm(A0); v1 = fsigm(A1); }
        gates_sh[0][tid] = v0;
        gates_sh[1][tid] = v1;
        __syncthreads();

        if (tid < 128) {
            float gi = gates_sh[bl][j];
            float gf = gates_sh[bl][HH + j];
            float gc = gates_sh[bl][2 * HH + j];
            float go = gates_sh[bl][3 * HH + j];
            c = fmaf(gf, c, gi * gc);
            float h = go * ftanh(c);
            h_sh[bl][j] = h;
            if (SMODE == 0)
                hout[((size_t)t * BB + b0 + bl) * HH + j] = h;
            if (SMODE == 1 && t == TT - 1)
                hout[(size_t)(b0 + bl) * HH + j] = h;
        }
        __syncthreads();
    }
}

// ---------------------------------------------------------------------------
extern "C" void kernel_launch(void* const* d_in, const int* in_sizes, int n_in,
                              void* d_out, int out_size)
{
    (void)in_sizes; (void)n_in; (void)out_size;
    const float* x     = (const float*)d_in[0];
    const float* eWih0 = (const float*)d_in[1];
    const float* eWhh0 = (const float*)d_in[2];
    const float* ebih0 = (const float*)d_in[3];
    const float* ebhh0 = (const float*)d_in[4];
    const float* eWih1 = (const float*)d_in[5];
    const float* eWhh1 = (const float*)d_in[6];
    const float* ebih1 = (const float*)d_in[7];
    const float* ebhh1 = (const float*)d_in[8];
    const float* dWih0 = (const float*)d_in[9];
    const float* dWhh0 = (const float*)d_in[10];
    const float* dbih0 = (const float*)d_in[11];
    const float* dbhh0 = (const float*)d_in[12];
    const float* dWih1 = (const float*)d_in[13];
    const float* dWhh1 = (const float*)d_in[14];
    const float* dbih1 = (const float*)d_in[15];
    const float* dbhh1 = (const float*)d_in[16];
    const float* fcW   = (const float*)d_in[17];
    const float* fcb   = (const float*)d_in[18];
    float* out = (float*)d_out;

    float *xgp, *hseqp, *latp, *xgcp;
    cudaGetSymbolAddress((void**)&xgp,   g_xg);
    cudaGetSymbolAddress((void**)&hseqp, g_hseq);
    cudaGetSymbolAddress((void**)&latp,  g_lat);
    cudaGetSymbolAddress((void**)&xgcp,  g_xgc);

    dim3 gbig(TT * BB / 128, GG / 64);  // (1024, 4)
    dim3 gsm(BB / 128, GG / 64);        // (4, 4)
    dim3 gscan(BB / 2);                 // 256 blocks, 2 batch each
    dim3 gfc(TT * BB / 128);            // 1024 blocks

    // Encoder layer 0
    xg_gemm<<<gbig, 256>>>(x, TT * 64, 64, eWih0, ebih0, ebhh0, xgp);
    lstm_scan<0, 0><<<gscan, 256>>>(xgp, eWhh0, hseqp);

    // Encoder layer 1 -> latent
    xg_gemm<<<gbig, 256>>>(hseqp, 64, BB * 64, eWih1, ebih1, ebhh1, xgp);
    lstm_scan<0, 1><<<gscan, 256>>>(xgp, eWhh1, latp);

    // Decoder layer 0 (constant input)
    xg_gemm<<<gsm, 256>>>(latp, 64, 0, dWih0, dbih0, dbhh0, xgcp);
    lstm_scan<1, 0><<<gscan, 256>>>(xgcp, dWhh0, hseqp);

    // Decoder layer 1
    xg_gemm<<<gbig, 256>>>(hseqp, 64, BB * 64, dWih1, dbih1, dbhh1, xgp);
    lstm_scan<0, 0><<<gscan, 256>>>(xgp, dWhh1, hseqp);

    // Output projection
    fc_gemm<<<gfc, 256>>>(hseqp, fcW, fcb, out);
}